// round 1
// baseline (speedup 1.0000x reference)
#include <cuda_runtime.h>
#include <cuda_bf16.h>
#include <math.h>
#include <stdint.h>

// ---------------- problem dims (fixed) ----------------
#define NN    50000
#define MM    1024
#define LL    3
#define EE    200000
#define HIDD  512
#define EMBD  256
#define VOC   512
#define NSLT  4
#define NSRT  5

// ---------------- scratch (static device globals; no allocs allowed) ------
__device__ float g_hA [(size_t)NN * EMBD];
__device__ float g_hB [(size_t)NN * EMBD];
__device__ float g_ctx[(size_t)NN * EMBD];
__device__ float g_S  [(size_t)NN * MM];     // attn logits / scatter tmp / head logits
__device__ float g_k  [MM * EMBD];
__device__ float g_kT [EMBD * MM];

// ---------------- SGEMM: C = relu?(alpha*A@B + Cin) ------------------------
// A[M,K], B[K,N] row-major. N % 128 == 0, K % 16 == 0, M arbitrary.
#define BM 128
#define BN 128
#define BK 16

template<bool ACC, bool RELU>
__global__ void __launch_bounds__(256)
sgemm_kernel(const float* __restrict__ A, const float* __restrict__ B,
             const float* __restrict__ Cin, float* __restrict__ D,
             int M, int N, int K, float alpha)
{
    __shared__ float As[2][BK][BM + 4];
    __shared__ float Bs[2][BK][BN];

    const int tid = threadIdx.x;
    const int tx  = tid & 15;
    const int ty  = tid >> 4;
    const int bm  = blockIdx.y * BM;
    const int bn  = blockIdx.x * BN;

    const int aRow = tid >> 2;          // 0..63
    const int aCol = (tid & 3) << 2;    // 0,4,8,12
    const int bRow = tid >> 5;          // 0..7
    const int bCol = (tid & 31) << 2;   // 0..124

    float4 aReg[2], bReg[2];
    float acc[8][8];
#pragma unroll
    for (int i = 0; i < 8; i++)
#pragma unroll
        for (int j = 0; j < 8; j++) acc[i][j] = 0.f;

    const int nkt = K >> 4;

    // prologue: tile 0
#pragma unroll
    for (int i = 0; i < 2; i++) {
        int row = aRow + i * 64;
        if (bm + row < M)
            aReg[i] = *(const float4*)(A + (size_t)(bm + row) * K + aCol);
        else
            aReg[i] = make_float4(0.f, 0.f, 0.f, 0.f);
        bReg[i] = *(const float4*)(B + (size_t)(bRow + i * 8) * N + bn + bCol);
    }
#pragma unroll
    for (int i = 0; i < 2; i++) {
        As[0][aCol + 0][aRow + i * 64] = aReg[i].x;
        As[0][aCol + 1][aRow + i * 64] = aReg[i].y;
        As[0][aCol + 2][aRow + i * 64] = aReg[i].z;
        As[0][aCol + 3][aRow + i * 64] = aReg[i].w;
        *(float4*)&Bs[0][bRow + i * 8][bCol] = bReg[i];
    }
    __syncthreads();

    for (int kt = 0; kt < nkt; kt++) {
        const int cur = kt & 1;
        if (kt + 1 < nkt) {
#pragma unroll
            for (int i = 0; i < 2; i++) {
                int row = aRow + i * 64;
                if (bm + row < M)
                    aReg[i] = *(const float4*)(A + (size_t)(bm + row) * K + (size_t)(kt + 1) * BK + aCol);
                else
                    aReg[i] = make_float4(0.f, 0.f, 0.f, 0.f);
                bReg[i] = *(const float4*)(B + (size_t)((kt + 1) * BK + bRow + i * 8) * N + bn + bCol);
            }
        }
#pragma unroll
        for (int kk = 0; kk < BK; kk++) {
            float a[8], b[8];
            *(float4*)&a[0] = *(const float4*)&As[cur][kk][ty * 4];
            *(float4*)&a[4] = *(const float4*)&As[cur][kk][64 + ty * 4];
            *(float4*)&b[0] = *(const float4*)&Bs[cur][kk][tx * 4];
            *(float4*)&b[4] = *(const float4*)&Bs[cur][kk][64 + tx * 4];
#pragma unroll
            for (int i = 0; i < 8; i++)
#pragma unroll
                for (int j = 0; j < 8; j++)
                    acc[i][j] += a[i] * b[j];
        }
        if (kt + 1 < nkt) {
            const int nxt = cur ^ 1;
#pragma unroll
            for (int i = 0; i < 2; i++) {
                As[nxt][aCol + 0][aRow + i * 64] = aReg[i].x;
                As[nxt][aCol + 1][aRow + i * 64] = aReg[i].y;
                As[nxt][aCol + 2][aRow + i * 64] = aReg[i].z;
                As[nxt][aCol + 3][aRow + i * 64] = aReg[i].w;
                *(float4*)&Bs[nxt][bRow + i * 8][bCol] = bReg[i];
            }
        }
        __syncthreads();
    }

    // epilogue
#pragma unroll
    for (int ih = 0; ih < 2; ih++) {
#pragma unroll
        for (int i = 0; i < 4; i++) {
            int row = bm + ih * 64 + ty * 4 + i;
            if (row >= M) continue;
#pragma unroll
            for (int jh = 0; jh < 2; jh++) {
                int col = bn + jh * 64 + tx * 4;
                float4 v;
                v.x = acc[ih * 4 + i][jh * 4 + 0] * alpha;
                v.y = acc[ih * 4 + i][jh * 4 + 1] * alpha;
                v.z = acc[ih * 4 + i][jh * 4 + 2] * alpha;
                v.w = acc[ih * 4 + i][jh * 4 + 3] * alpha;
                if (ACC) {
                    float4 c = *(const float4*)(Cin + (size_t)row * N + col);
                    v.x += c.x; v.y += c.y; v.z += c.z; v.w += c.w;
                }
                if (RELU) {
                    v.x = fmaxf(v.x, 0.f); v.y = fmaxf(v.y, 0.f);
                    v.z = fmaxf(v.z, 0.f); v.w = fmaxf(v.w, 0.f);
                }
                *(float4*)(D + (size_t)row * N + col) = v;
            }
        }
    }
}

// ---------------- small helper kernels -------------------------------------
__global__ void embed_kernel(const int* __restrict__ tx,
                             const float* __restrict__ table,
                             float* __restrict__ h)
{
    int idx = blockIdx.x * blockDim.x + threadIdx.x;  // NN*64 work items
    if (idx >= NN * (EMBD / 4)) return;
    int n = idx >> 6;
    int c = idx & 63;
    int i0 = tx[n * 3 + 0], i1 = tx[n * 3 + 1], i2 = tx[n * 3 + 2];
    const float4* t4 = (const float4*)table;
    float4 a = t4[(size_t)i0 * 64 + c];
    float4 b = t4[(size_t)i1 * 64 + c];
    float4 d = t4[(size_t)i2 * 64 + c];
    float4 o;
    o.x = a.x + b.x + d.x; o.y = a.y + b.y + d.y;
    o.z = a.z + b.z + d.z; o.w = a.w + b.w + d.w;
    ((float4*)h)[idx] = o;
}

__global__ void transpose_k(const float* __restrict__ k, float* __restrict__ kT)
{
    int i = blockIdx.x * blockDim.x + threadIdx.x;
    if (i >= MM * EMBD) return;
    int r = i >> 8;        // 0..1023
    int c = i & 255;       // 0..255
    kT[(size_t)c * MM + r] = k[i];
}

__global__ void zero_kernel(float4* __restrict__ p, int n4)
{
    int i = blockIdx.x * blockDim.x + threadIdx.x;
    if (i < n4) p[i] = make_float4(0.f, 0.f, 0.f, 0.f);
}

__global__ void scatter_edges(const int* __restrict__ ei, const int* __restrict__ et,
                              const float* __restrict__ h, float* __restrict__ tmp)
{
    int idx = blockIdx.x * blockDim.x + threadIdx.x;  // EE*64
    if (idx >= EE * (EMBD / 4)) return;
    int e = idx >> 6;
    int c = idx & 63;
    int src = ei[e];
    int tgt = ei[EE + e];
    int t   = et[e];
    float4 v = ((const float4*)(h + (size_t)src * EMBD))[c];
    float* dst = tmp + ((size_t)tgt * NSLT + t) * EMBD + (size_t)c * 4;
    atomicAdd(dst + 0, v.x);
    atomicAdd(dst + 1, v.y);
    atomicAdd(dst + 2, v.z);
    atomicAdd(dst + 3, v.w);
}

__device__ __forceinline__ float warp_max(float v) {
#pragma unroll
    for (int o = 16; o; o >>= 1) v = fmaxf(v, __shfl_xor_sync(0xffffffffu, v, o));
    return v;
}
__device__ __forceinline__ float warp_sum(float v) {
#pragma unroll
    for (int o = 16; o; o >>= 1) v += __shfl_xor_sync(0xffffffffu, v, o);
    return v;
}

// in-place softmax over rows of width 1024; 256 threads/block, 1 block/row
__global__ void softmax1024(float* __restrict__ S)
{
    __shared__ float shm[8];
    __shared__ float shs[8];
    size_t row = blockIdx.x;
    float4* p = (float4*)(S + row * MM);
    int tid = threadIdx.x;
    int wid = tid >> 5, lane = tid & 31;

    float4 x = p[tid];
    float m = fmaxf(fmaxf(x.x, x.y), fmaxf(x.z, x.w));
    m = warp_max(m);
    if (lane == 0) shm[wid] = m;
    __syncthreads();
    if (tid == 0) {
        float v = shm[0];
#pragma unroll
        for (int i = 1; i < 8; i++) v = fmaxf(v, shm[i]);
        shm[0] = v;
    }
    __syncthreads();
    m = shm[0];

    float4 e;
    e.x = expf(x.x - m); e.y = expf(x.y - m);
    e.z = expf(x.z - m); e.w = expf(x.w - m);
    float s = e.x + e.y + e.z + e.w;
    s = warp_sum(s);
    if (lane == 0) shs[wid] = s;
    __syncthreads();
    if (tid == 0) {
        float v = 0.f;
#pragma unroll
        for (int i = 0; i < 8; i++) v += shs[i];
        shs[0] = v;
    }
    __syncthreads();
    float inv = 1.f / shs[0];
    e.x *= inv; e.y *= inv; e.z *= inv; e.w *= inv;
    p[tid] = e;
}

// log_softmax over rows of width 512 with bias; 128 threads/block, 1 block/row
__global__ void log_softmax512(const float* __restrict__ logits,
                               const float* __restrict__ bias,
                               float* __restrict__ out)
{
    __shared__ float shm[4];
    __shared__ float shs[4];
    size_t row = blockIdx.x;
    const float4* p = (const float4*)(logits + row * VOC);
    const float4* b4 = (const float4*)bias;
    float4* o = (float4*)(out + row * VOC);
    int tid = threadIdx.x;
    int wid = tid >> 5, lane = tid & 31;

    float4 x = p[tid];
    float4 b = b4[tid];
    x.x += b.x; x.y += b.y; x.z += b.z; x.w += b.w;

    float m = fmaxf(fmaxf(x.x, x.y), fmaxf(x.z, x.w));
    m = warp_max(m);
    if (lane == 0) shm[wid] = m;
    __syncthreads();
    if (tid == 0) {
        float v = fmaxf(fmaxf(shm[0], shm[1]), fmaxf(shm[2], shm[3]));
        shm[0] = v;
    }
    __syncthreads();
    m = shm[0];

    float s = expf(x.x - m) + expf(x.y - m) + expf(x.z - m) + expf(x.w - m);
    s = warp_sum(s);
    if (lane == 0) shs[wid] = s;
    __syncthreads();
    if (tid == 0) shs[0] = shs[0] + shs[1] + shs[2] + shs[3];
    __syncthreads();
    float lse = m + logf(shs[0]);

    x.x -= lse; x.y -= lse; x.z -= lse; x.w -= lse;
    o[tid] = x;
}

// edge head: one warp per edge
__global__ void edge_head(const float* __restrict__ h, const int* __restrict__ ei,
                          const float* __restrict__ Wg, const float* __restrict__ bg,
                          float* __restrict__ out)
{
    __shared__ float sW[2 * EMBD * NSRT];
    __shared__ float sb[NSRT];
    for (int i = threadIdx.x; i < 2 * EMBD * NSRT; i += blockDim.x) sW[i] = Wg[i];
    if (threadIdx.x < NSRT) sb[threadIdx.x] = bg[threadIdx.x];
    __syncthreads();

    int e = blockIdx.x * 8 + (threadIdx.x >> 5);
    int lane = threadIdx.x & 31;
    if (e >= EE) return;
    int src = ei[e];
    int tgt = ei[EE + e];
    const float* hs = h + (size_t)src * EMBD;
    const float* ht = h + (size_t)tgt * EMBD;

    float s[NSRT] = {0.f, 0.f, 0.f, 0.f, 0.f};
    for (int d = lane; d < EMBD; d += 32) {
        float a = hs[d];
        float b = ht[d];
#pragma unroll
        for (int r = 0; r < NSRT; r++)
            s[r] += a * sW[d * NSRT + r] + b * sW[(EMBD + d) * NSRT + r];
    }
#pragma unroll
    for (int r = 0; r < NSRT; r++) s[r] = warp_sum(s[r]);

    if (lane == 0) {
#pragma unroll
        for (int r = 0; r < NSRT; r++) s[r] += sb[r];
        float m = s[0];
#pragma unroll
        for (int r = 1; r < NSRT; r++) m = fmaxf(m, s[r]);
        float sum = 0.f;
#pragma unroll
        for (int r = 0; r < NSRT; r++) sum += expf(s[r] - m);
        float lse = m + logf(sum);
#pragma unroll
        for (int r = 0; r < NSRT; r++)
            out[(size_t)e * NSRT + r] = s[r] - lse;
    }
}

// ---------------- host orchestration ---------------------------------------
static void run_sgemm(const float* A, const float* B, const float* Cin, float* D,
                      int M, int N, int K, float alpha, bool acc, bool relu)
{
    dim3 grid(N / BN, (M + BM - 1) / BM);
    if (acc) {
        if (relu) sgemm_kernel<true, true ><<<grid, 256>>>(A, B, Cin, D, M, N, K, alpha);
        else      sgemm_kernel<true, false><<<grid, 256>>>(A, B, Cin, D, M, N, K, alpha);
    } else {
        sgemm_kernel<false, false><<<grid, 256>>>(A, B, nullptr, D, M, N, K, alpha);
    }
}

static void run_layer(const float* hin, float* hout,
                      const float* x, const int* ei, const int* et,
                      const float* W_h, const float* W_rel, const float* W_src,
                      float* kbuf, float* kTbuf, float* Sbuf, float* ctxbuf)
{
    // k = x @ W_src   [1024,256]  K=512
    run_sgemm(x, W_src, nullptr, kbuf, MM, EMBD, HIDD, 1.f, false, false);
    transpose_k<<<(MM * EMBD + 255) / 256, 256>>>(kbuf, kTbuf);
    // S = (h @ kT) / 16   [N,1024]  K=256
    run_sgemm(hin, kTbuf, nullptr, Sbuf, NN, MM, EMBD, 0.0625f, false, false);
    softmax1024<<<NN, 256>>>(Sbuf);
    // ctx = S @ k   [N,256]  K=1024
    run_sgemm(Sbuf, kbuf, nullptr, ctxbuf, NN, EMBD, MM, 1.f, false, false);
    // tmp scatter: tmp[tgt,type,:] += h[src,:]
    zero_kernel<<<(NN * MM / 4 + 255) / 256, 256>>>((float4*)Sbuf, NN * MM / 4);
    scatter_edges<<<(EE * (EMBD / 4) + 255) / 256, 256>>>(ei, et, hin, Sbuf);
    // ctx += tmp_flat @ W_rel_flat   [N,256]  K=1024
    run_sgemm(Sbuf, W_rel, ctxbuf, ctxbuf, NN, EMBD, NSLT * EMBD, 1.f, true, false);
    // hout = relu(hin @ W_h + ctx)   [N,256]  K=256
    run_sgemm(hin, W_h, ctxbuf, hout, NN, EMBD, EMBD, 1.f, true, true);
}

extern "C" void kernel_launch(void* const* d_in, const int* in_sizes, int n_in,
                              void* d_out, int out_size)
{
    const int*   tgt_x  = (const int*)  d_in[0];
    const float* x      = (const float*)d_in[1];
    const int*   ei     = (const int*)  d_in[2];
    const int*   et     = (const int*)  d_in[3];
    const float* table  = (const float*)d_in[4];
    const float* W_h1   = (const float*)d_in[5];
    const float* W_rel1 = (const float*)d_in[6];
    const float* W_src1 = (const float*)d_in[7];
    const float* W_h3   = (const float*)d_in[8];
    const float* W_rel3 = (const float*)d_in[9];
    const float* W_src3 = (const float*)d_in[10];
    const float* Wz     = (const float*)d_in[11];
    const float* bz     = (const float*)d_in[12];
    const float* Wg     = (const float*)d_in[13];
    const float* bg     = (const float*)d_in[14];
    float* out = (float*)d_out;

    float *hA, *hB, *ctx, *S, *k, *kT;
    cudaGetSymbolAddress((void**)&hA,  g_hA);
    cudaGetSymbolAddress((void**)&hB,  g_hB);
    cudaGetSymbolAddress((void**)&ctx, g_ctx);
    cudaGetSymbolAddress((void**)&S,   g_S);
    cudaGetSymbolAddress((void**)&k,   g_k);
    cudaGetSymbolAddress((void**)&kT,  g_kT);

    // h0 = sum_l embed_table[tgt_x[:,l]]
    embed_kernel<<<(NN * (EMBD / 4) + 255) / 256, 256>>>(tgt_x, table, hA);

    run_layer(hA, hB, x, ei, et, W_h1, W_rel1, W_src1, k, kT, S, ctx);
    run_layer(hB, hA, x, ei, et, W_h1, W_rel1, W_src1, k, kT, S, ctx);
    run_layer(hA, hB, x, ei, et, W_h3, W_rel3, W_src3, k, kT, S, ctx);

    // node head: logits = h @ Wz (bias + log_softmax fused in next kernel)
    run_sgemm(hB, Wz, nullptr, S, NN, VOC, EMBD, 1.f, false, false);
    log_softmax512<<<NN, 128>>>(S, bz, out);

    // edge head
    edge_head<<<(EE + 7) / 8, 256>>>(hB, ei, Wg, bg, out + (size_t)NN * VOC);
}

// round 3
// speedup vs baseline: 2.4183x; 2.4183x over previous
#include <cuda_runtime.h>
#include <math.h>
#include <stdint.h>

// ---------------- problem dims (fixed) ----------------
#define NN    50000
#define MM    1024
#define EE    200000
#define HIDD  512
#define EMBD  256
#define VOC   512
#define NSLT  4
#define NSRT  5

// ---------------- scratch (static device globals) --------------------------
__device__ float g_hA [(size_t)NN * EMBD];
__device__ float g_hB [(size_t)NN * EMBD];
__device__ float g_ctx[(size_t)NN * EMBD];
__device__ float g_S  [(size_t)NN * MM];     // attn logits / scatter tmp / head logits
__device__ float g_k  [MM * EMBD];
__device__ float g_kT [EMBD * MM];

// ---------------- tf32 helpers ---------------------------------------------
__device__ __forceinline__ float to_tf32(float x) {
    uint32_t u;
    asm("cvt.rna.tf32.f32 %0, %1;" : "=r"(u) : "f"(x));
    return __uint_as_float(u);
}

__device__ __forceinline__ void mma_tf32(float& c0, float& c1, float& c2, float& c3,
                                         uint32_t a0, uint32_t a1, uint32_t a2, uint32_t a3,
                                         uint32_t b0, uint32_t b1)
{
    asm volatile(
        "mma.sync.aligned.m16n8k8.row.col.f32.tf32.tf32.f32 "
        "{%0,%1,%2,%3}, {%4,%5,%6,%7}, {%8,%9}, {%0,%1,%2,%3};"
        : "+f"(c0), "+f"(c1), "+f"(c2), "+f"(c3)
        : "r"(a0), "r"(a1), "r"(a2), "r"(a3), "r"(b0), "r"(b1));
}

// ---------------- tf32 tensor GEMM: D = relu?(alpha*A@B + Cin) -------------
// A[M,K], B[K,N] row-major fp32. N % 128 == 0, K % 16 == 0, M arbitrary.
// CTA tile 128x128x16, 8 warps (2x4), warp tile 64x32, mma m16n8k8.
#define BM 128
#define BN 128
#define BK 16
#define APAD 12     // row len 140: (140 % 32)=12 -> conflict-free frag loads
#define BPAD 8      // row len 136: (136 % 32)=8  -> conflict-free frag loads

template<bool ACC, bool RELU>
__global__ void __launch_bounds__(256)
sgemm_kernel(const float* __restrict__ A, const float* __restrict__ B,
             const float* __restrict__ Cin, float* __restrict__ D,
             int M, int N, int K, float alpha)
{
    __shared__ float As[2][BK][BM + APAD];
    __shared__ float Bs[2][BK][BN + BPAD];

    const int tid  = threadIdx.x;
    const int bm   = blockIdx.y * BM;
    const int bn   = blockIdx.x * BN;

    const int warp = tid >> 5;
    const int lane = tid & 31;
    const int wm   = (warp >> 2) * 64;   // warp row offset: 0 / 64
    const int wn   = (warp & 3) * 32;    // warp col offset: 0/32/64/96
    const int g    = lane >> 2;          // 0..7
    const int tg   = lane & 3;           // 0..3

    // global->smem mapping (same as proven round-1 kernel)
    const int aRow = tid >> 2;           // 0..63
    const int aCol = (tid & 3) << 2;     // 0,4,8,12
    const int bRow = tid >> 5;           // 0..7
    const int bCol = (tid & 31) << 2;    // 0..124

    float4 aReg[2], bReg[2];
    float c[4][4][4];
#pragma unroll
    for (int i = 0; i < 4; i++)
#pragma unroll
        for (int j = 0; j < 4; j++)
#pragma unroll
            for (int r = 0; r < 4; r++) c[i][j][r] = 0.f;

    const int nkt = K >> 4;

    // ---- prologue: load tile 0 ----
#pragma unroll
    for (int i = 0; i < 2; i++) {
        int row = aRow + i * 64;
        if (bm + row < M)
            aReg[i] = *(const float4*)(A + (size_t)(bm + row) * K + aCol);
        else
            aReg[i] = make_float4(0.f, 0.f, 0.f, 0.f);
        bReg[i] = *(const float4*)(B + (size_t)(bRow + i * 8) * N + bn + bCol);
    }
#pragma unroll
    for (int i = 0; i < 2; i++) {
        As[0][aCol + 0][aRow + i * 64] = to_tf32(aReg[i].x);
        As[0][aCol + 1][aRow + i * 64] = to_tf32(aReg[i].y);
        As[0][aCol + 2][aRow + i * 64] = to_tf32(aReg[i].z);
        As[0][aCol + 3][aRow + i * 64] = to_tf32(aReg[i].w);
        float4 bv;
        bv.x = to_tf32(bReg[i].x); bv.y = to_tf32(bReg[i].y);
        bv.z = to_tf32(bReg[i].z); bv.w = to_tf32(bReg[i].w);
        *(float4*)&Bs[0][bRow + i * 8][bCol] = bv;
    }
    __syncthreads();

    for (int kt = 0; kt < nkt; kt++) {
        const int cur = kt & 1;
        if (kt + 1 < nkt) {
#pragma unroll
            for (int i = 0; i < 2; i++) {
                int row = aRow + i * 64;
                if (bm + row < M)
                    aReg[i] = *(const float4*)(A + (size_t)(bm + row) * K + (size_t)(kt + 1) * BK + aCol);
                else
                    aReg[i] = make_float4(0.f, 0.f, 0.f, 0.f);
                bReg[i] = *(const float4*)(B + (size_t)((kt + 1) * BK + bRow + i * 8) * N + bn + bCol);
            }
        }

        // ---- compute on current tile: 2 k-steps of 8 ----
#pragma unroll
        for (int ks = 0; ks < 2; ks++) {
            const int k0 = ks * 8;
            uint32_t a[4][4], b[4][2];
#pragma unroll
            for (int i = 0; i < 4; i++) {
                int m = wm + i * 16 + g;
                a[i][0] = __float_as_uint(As[cur][k0 + tg    ][m    ]);
                a[i][1] = __float_as_uint(As[cur][k0 + tg    ][m + 8]);
                a[i][2] = __float_as_uint(As[cur][k0 + tg + 4][m    ]);
                a[i][3] = __float_as_uint(As[cur][k0 + tg + 4][m + 8]);
            }
#pragma unroll
            for (int j = 0; j < 4; j++) {
                int n = wn + j * 8 + g;
                b[j][0] = __float_as_uint(Bs[cur][k0 + tg    ][n]);
                b[j][1] = __float_as_uint(Bs[cur][k0 + tg + 4][n]);
            }
#pragma unroll
            for (int i = 0; i < 4; i++)
#pragma unroll
                for (int j = 0; j < 4; j++)
                    mma_tf32(c[i][j][0], c[i][j][1], c[i][j][2], c[i][j][3],
                             a[i][0], a[i][1], a[i][2], a[i][3],
                             b[j][0], b[j][1]);
        }

        if (kt + 1 < nkt) {
            const int nxt = cur ^ 1;
#pragma unroll
            for (int i = 0; i < 2; i++) {
                As[nxt][aCol + 0][aRow + i * 64] = to_tf32(aReg[i].x);
                As[nxt][aCol + 1][aRow + i * 64] = to_tf32(aReg[i].y);
                As[nxt][aCol + 2][aRow + i * 64] = to_tf32(aReg[i].z);
                As[nxt][aCol + 3][aRow + i * 64] = to_tf32(aReg[i].w);
                float4 bv;
                bv.x = to_tf32(bReg[i].x); bv.y = to_tf32(bReg[i].y);
                bv.z = to_tf32(bReg[i].z); bv.w = to_tf32(bReg[i].w);
                *(float4*)&Bs[nxt][bRow + i * 8][bCol] = bv;
            }
        }
        __syncthreads();
    }

    // ---- epilogue: C fragment layout m16n8: (g, 2tg),(g, 2tg+1),(g+8, ...) ----
#pragma unroll
    for (int i = 0; i < 4; i++) {
        int r0 = bm + wm + i * 16 + g;
        int r1 = r0 + 8;
#pragma unroll
        for (int j = 0; j < 4; j++) {
            int col = bn + wn + j * 8 + 2 * tg;
            if (r0 < M) {
                float2 v;
                v.x = c[i][j][0] * alpha;
                v.y = c[i][j][1] * alpha;
                if (ACC) {
                    float2 cc = *(const float2*)(Cin + (size_t)r0 * N + col);
                    v.x += cc.x; v.y += cc.y;
                }
                if (RELU) { v.x = fmaxf(v.x, 0.f); v.y = fmaxf(v.y, 0.f); }
                *(float2*)(D + (size_t)r0 * N + col) = v;
            }
            if (r1 < M) {
                float2 v;
                v.x = c[i][j][2] * alpha;
                v.y = c[i][j][3] * alpha;
                if (ACC) {
                    float2 cc = *(const float2*)(Cin + (size_t)r1 * N + col);
                    v.x += cc.x; v.y += cc.y;
                }
                if (RELU) { v.x = fmaxf(v.x, 0.f); v.y = fmaxf(v.y, 0.f); }
                *(float2*)(D + (size_t)r1 * N + col) = v;
            }
        }
    }
}

// ---------------- small helper kernels -------------------------------------
__global__ void embed_kernel(const int* __restrict__ tx,
                             const float* __restrict__ table,
                             float* __restrict__ h)
{
    int idx = blockIdx.x * blockDim.x + threadIdx.x;  // NN*64 work items
    if (idx >= NN * (EMBD / 4)) return;
    int n = idx >> 6;
    int c = idx & 63;
    int i0 = tx[n * 3 + 0], i1 = tx[n * 3 + 1], i2 = tx[n * 3 + 2];
    const float4* t4 = (const float4*)table;
    float4 a = t4[(size_t)i0 * 64 + c];
    float4 b = t4[(size_t)i1 * 64 + c];
    float4 d = t4[(size_t)i2 * 64 + c];
    float4 o;
    o.x = a.x + b.x + d.x; o.y = a.y + b.y + d.y;
    o.z = a.z + b.z + d.z; o.w = a.w + b.w + d.w;
    ((float4*)h)[idx] = o;
}

__global__ void transpose_k(const float* __restrict__ k, float* __restrict__ kT)
{
    int i = blockIdx.x * blockDim.x + threadIdx.x;
    if (i >= MM * EMBD) return;
    int r = i >> 8;        // 0..1023
    int c = i & 255;       // 0..255
    kT[(size_t)c * MM + r] = k[i];
}

__global__ void zero_kernel(float4* __restrict__ p, int n4)
{
    int i = blockIdx.x * blockDim.x + threadIdx.x;
    if (i < n4) p[i] = make_float4(0.f, 0.f, 0.f, 0.f);
}

__global__ void scatter_edges(const int* __restrict__ ei, const int* __restrict__ et,
                              const float* __restrict__ h, float* __restrict__ tmp)
{
    int idx = blockIdx.x * blockDim.x + threadIdx.x;  // EE*64
    if (idx >= EE * (EMBD / 4)) return;
    int e = idx >> 6;
    int c = idx & 63;
    int src = ei[e];
    int tgt = ei[EE + e];
    int t   = et[e];
    float4 v = ((const float4*)(h + (size_t)src * EMBD))[c];
    float* dst = tmp + ((size_t)tgt * NSLT + t) * EMBD + (size_t)c * 4;
    atomicAdd(dst + 0, v.x);
    atomicAdd(dst + 1, v.y);
    atomicAdd(dst + 2, v.z);
    atomicAdd(dst + 3, v.w);
}

__device__ __forceinline__ float warp_max(float v) {
#pragma unroll
    for (int o = 16; o; o >>= 1) v = fmaxf(v, __shfl_xor_sync(0xffffffffu, v, o));
    return v;
}
__device__ __forceinline__ float warp_sum(float v) {
#pragma unroll
    for (int o = 16; o; o >>= 1) v += __shfl_xor_sync(0xffffffffu, v, o);
    return v;
}

// in-place softmax over rows of width 1024; 256 threads/block, 1 block/row
__global__ void softmax1024(float* __restrict__ S)
{
    __shared__ float shm[8];
    __shared__ float shs[8];
    size_t row = blockIdx.x;
    float4* p = (float4*)(S + row * MM);
    int tid = threadIdx.x;
    int wid = tid >> 5, lane = tid & 31;

    float4 x = p[tid];
    float m = fmaxf(fmaxf(x.x, x.y), fmaxf(x.z, x.w));
    m = warp_max(m);
    if (lane == 0) shm[wid] = m;
    __syncthreads();
    if (tid == 0) {
        float v = shm[0];
#pragma unroll
        for (int i = 1; i < 8; i++) v = fmaxf(v, shm[i]);
        shm[0] = v;
    }
    __syncthreads();
    m = shm[0];

    float4 e;
    e.x = expf(x.x - m); e.y = expf(x.y - m);
    e.z = expf(x.z - m); e.w = expf(x.w - m);
    float s = e.x + e.y + e.z + e.w;
    s = warp_sum(s);
    if (lane == 0) shs[wid] = s;
    __syncthreads();
    if (tid == 0) {
        float v = 0.f;
#pragma unroll
        for (int i = 0; i < 8; i++) v += shs[i];
        shs[0] = v;
    }
    __syncthreads();
    float inv = 1.f / shs[0];
    e.x *= inv; e.y *= inv; e.z *= inv; e.w *= inv;
    p[tid] = e;
}

// log_softmax over rows of width 512 with bias; 128 threads/block, 1 block/row
__global__ void log_softmax512(const float* __restrict__ logits,
                               const float* __restrict__ bias,
                               float* __restrict__ out)
{
    __shared__ float shm[4];
    __shared__ float shs[4];
    size_t row = blockIdx.x;
    const float4* p = (const float4*)(logits + row * VOC);
    const float4* b4 = (const float4*)bias;
    float4* o = (float4*)(out + row * VOC);
    int tid = threadIdx.x;
    int wid = tid >> 5, lane = tid & 31;

    float4 x = p[tid];
    float4 b = b4[tid];
    x.x += b.x; x.y += b.y; x.z += b.z; x.w += b.w;

    float m = fmaxf(fmaxf(x.x, x.y), fmaxf(x.z, x.w));
    m = warp_max(m);
    if (lane == 0) shm[wid] = m;
    __syncthreads();
    if (tid == 0) shm[0] = fmaxf(fmaxf(shm[0], shm[1]), fmaxf(shm[2], shm[3]));
    __syncthreads();
    m = shm[0];

    float s = expf(x.x - m) + expf(x.y - m) + expf(x.z - m) + expf(x.w - m);
    s = warp_sum(s);
    if (lane == 0) shs[wid] = s;
    __syncthreads();
    if (tid == 0) shs[0] = shs[0] + shs[1] + shs[2] + shs[3];
    __syncthreads();
    float lse = m + logf(shs[0]);

    x.x -= lse; x.y -= lse; x.z -= lse; x.w -= lse;
    o[tid] = x;
}

// edge head: one warp per edge
__global__ void edge_head(const float* __restrict__ h, const int* __restrict__ ei,
                          const float* __restrict__ Wg, const float* __restrict__ bg,
                          float* __restrict__ out)
{
    __shared__ float sW[2 * EMBD * NSRT];
    __shared__ float sb[NSRT];
    for (int i = threadIdx.x; i < 2 * EMBD * NSRT; i += blockDim.x) sW[i] = Wg[i];
    if (threadIdx.x < NSRT) sb[threadIdx.x] = bg[threadIdx.x];
    __syncthreads();

    int e = blockIdx.x * 8 + (threadIdx.x >> 5);
    int lane = threadIdx.x & 31;
    if (e >= EE) return;
    int src = ei[e];
    int tgt = ei[EE + e];
    const float* hs = h + (size_t)src * EMBD;
    const float* ht = h + (size_t)tgt * EMBD;

    float s[NSRT] = {0.f, 0.f, 0.f, 0.f, 0.f};
    for (int d = lane; d < EMBD; d += 32) {
        float a = hs[d];
        float b = ht[d];
#pragma unroll
        for (int r = 0; r < NSRT; r++)
            s[r] += a * sW[d * NSRT + r] + b * sW[(EMBD + d) * NSRT + r];
    }
#pragma unroll
    for (int r = 0; r < NSRT; r++) s[r] = warp_sum(s[r]);

    if (lane == 0) {
#pragma unroll
        for (int r = 0; r < NSRT; r++) s[r] += sb[r];
        float m = s[0];
#pragma unroll
        for (int r = 1; r < NSRT; r++) m = fmaxf(m, s[r]);
        float sum = 0.f;
#pragma unroll
        for (int r = 0; r < NSRT; r++) sum += expf(s[r] - m);
        float lse = m + logf(sum);
#pragma unroll
        for (int r = 0; r < NSRT; r++)
            out[(size_t)e * NSRT + r] = s[r] - lse;
    }
}

// ---------------- host orchestration ---------------------------------------
static void run_sgemm(const float* A, const float* B, const float* Cin, float* D,
                      int M, int N, int K, float alpha, bool acc, bool relu)
{
    dim3 grid(N / BN, (M + BM - 1) / BM);
    if (acc) {
        if (relu) sgemm_kernel<true, true ><<<grid, 256>>>(A, B, Cin, D, M, N, K, alpha);
        else      sgemm_kernel<true, false><<<grid, 256>>>(A, B, Cin, D, M, N, K, alpha);
    } else {
        sgemm_kernel<false, false><<<grid, 256>>>(A, B, nullptr, D, M, N, K, alpha);
    }
}

static void run_layer(const float* hin, float* hout,
                      const float* x, const int* ei, const int* et,
                      const float* W_h, const float* W_rel, const float* W_src,
                      float* kbuf, float* kTbuf, float* Sbuf, float* ctxbuf,
                      bool compute_k)
{
    // k = x @ W_src   [1024,256]  K=512   (layers 1&2 share weights: compute once)
    if (compute_k) {
        run_sgemm(x, W_src, nullptr, kbuf, MM, EMBD, HIDD, 1.f, false, false);
        transpose_k<<<(MM * EMBD + 255) / 256, 256>>>(kbuf, kTbuf);
    }
    // S = (h @ kT) / 16   [N,1024]  K=256
    run_sgemm(hin, kTbuf, nullptr, Sbuf, NN, MM, EMBD, 0.0625f, false, false);
    softmax1024<<<NN, 256>>>(Sbuf);
    // ctx = S @ k   [N,256]  K=1024
    run_sgemm(Sbuf, kbuf, nullptr, ctxbuf, NN, EMBD, MM, 1.f, false, false);
    // tmp scatter: tmp[tgt,type,:] += h[src,:]
    zero_kernel<<<(NN * MM / 4 + 255) / 256, 256>>>((float4*)Sbuf, NN * MM / 4);
    scatter_edges<<<(EE * (EMBD / 4) + 255) / 256, 256>>>(ei, et, hin, Sbuf);
    // ctx += tmp_flat @ W_rel_flat   [N,256]  K=1024
    run_sgemm(Sbuf, W_rel, ctxbuf, ctxbuf, NN, EMBD, NSLT * EMBD, 1.f, true, false);
    // hout = relu(hin @ W_h + ctx)   [N,256]  K=256
    run_sgemm(hin, W_h, ctxbuf, hout, NN, EMBD, EMBD, 1.f, true, true);
}

extern "C" void kernel_launch(void* const* d_in, const int* in_sizes, int n_in,
                              void* d_out, int out_size)
{
    const int*   tgt_x  = (const int*)  d_in[0];
    const float* x      = (const float*)d_in[1];
    const int*   ei     = (const int*)  d_in[2];
    const int*   et     = (const int*)  d_in[3];
    const float* table  = (const float*)d_in[4];
    const float* W_h1   = (const float*)d_in[5];
    const float* W_rel1 = (const float*)d_in[6];
    const float* W_src1 = (const float*)d_in[7];
    const float* W_h3   = (const float*)d_in[8];
    const float* W_rel3 = (const float*)d_in[9];
    const float* W_src3 = (const float*)d_in[10];
    const float* Wz     = (const float*)d_in[11];
    const float* bz     = (const float*)d_in[12];
    const float* Wg     = (const float*)d_in[13];
    const float* bg     = (const float*)d_in[14];
    float* out = (float*)d_out;

    float *hA, *hB, *ctx, *S, *k, *kT;
    cudaGetSymbolAddress((void**)&hA,  g_hA);
    cudaGetSymbolAddress((void**)&hB,  g_hB);
    cudaGetSymbolAddress((void**)&ctx, g_ctx);
    cudaGetSymbolAddress((void**)&S,   g_S);
    cudaGetSymbolAddress((void**)&k,   g_k);
    cudaGetSymbolAddress((void**)&kT,  g_kT);

    // h0 = sum_l embed_table[tgt_x[:,l]]
    embed_kernel<<<(NN * (EMBD / 4) + 255) / 256, 256>>>(tgt_x, table, hA);

    run_layer(hA, hB, x, ei, et, W_h1, W_rel1, W_src1, k, kT, S, ctx, true);
    run_layer(hB, hA, x, ei, et, W_h1, W_rel1, W_src1, k, kT, S, ctx, false);
    run_layer(hA, hB, x, ei, et, W_h3, W_rel3, W_src3, k, kT, S, ctx, true);

    // node head: logits = h @ Wz (bias + log_softmax fused in next kernel)
    run_sgemm(hB, Wz, nullptr, S, NN, VOC, EMBD, 1.f, false, false);
    log_softmax512<<<NN, 128>>>(S, bz, out);

    // edge head
    edge_head<<<(EE + 7) / 8, 256>>>(hB, ei, Wg, bg, out + (size_t)NN * VOC);
}

// round 6
// speedup vs baseline: 2.7148x; 1.1226x over previous
#include <cuda_runtime.h>
#include <math.h>
#include <stdint.h>

// ---------------- problem dims (fixed) ----------------
#define NN    50000
#define MM    1024
#define EE    200000
#define HIDD  512
#define EMBD  256
#define VOC   512
#define NSLT  4
#define NSRT  5

// ---------------- scratch (static device globals) --------------------------
__device__ float g_hA [(size_t)NN * EMBD];
__device__ float g_hB [(size_t)NN * EMBD];
__device__ float g_ctx[(size_t)NN * EMBD];
__device__ float g_S  [(size_t)NN * MM];     // attn logits / scatter tmp / head logits
__device__ float g_k  [MM * EMBD];
__device__ float g_kT [EMBD * MM];

// ---------------- mma / cp.async helpers -----------------------------------
__device__ __forceinline__ void mma_tf32(float& c0, float& c1, float& c2, float& c3,
                                         uint32_t a0, uint32_t a1, uint32_t a2, uint32_t a3,
                                         uint32_t b0, uint32_t b1)
{
    asm volatile(
        "mma.sync.aligned.m16n8k8.row.col.f32.tf32.tf32.f32 "
        "{%0,%1,%2,%3}, {%4,%5,%6,%7}, {%8,%9}, {%0,%1,%2,%3};"
        : "+f"(c0), "+f"(c1), "+f"(c2), "+f"(c3)
        : "r"(a0), "r"(a1), "r"(a2), "r"(a3), "r"(b0), "r"(b1));
}

__device__ __forceinline__ void cp_async16(uint32_t dst, const void* src, bool valid)
{
    int sz = valid ? 16 : 0;
    asm volatile("cp.async.cg.shared.global [%0], [%1], 16, %2;"
                 :: "r"(dst), "l"(src), "r"(sz) : "memory");
}
#define CP_COMMIT() asm volatile("cp.async.commit_group;" ::: "memory")
#define CP_WAIT1()  asm volatile("cp.async.wait_group 1;" ::: "memory")

// ---------------- tf32 tensor GEMM: D = relu?(alpha*A@B + Cin) -------------
// A[M,K], B[K,N] row-major fp32. N % 128 == 0, K % 16 == 0 (and K/16 >= 3),
// M arbitrary. CTA tile 128x128x16, 8 warps (2x4), warp tile 64x32, m16n8k8.
// 3-stage cp.async pipeline. A smem [128][20] row-major, B smem [16][136].
#define BM 128
#define BN 128
#define BK 16
#define AROW 20            // 16 + 4 pad: (20g+tg) mod 32 distinct -> no conflicts
#define BROW 136           // 128 + 8 pad: (8tg+g) mod 32 distinct -> no conflicts
#define A_STAGE (BM * AROW)            // 2560 floats
#define B_STAGE (BK * BROW)            // 2176 floats
#define B_BASE  (3 * A_STAGE)          // 7680
#define SMEM_FLOATS (3 * (A_STAGE + B_STAGE))
#define SMEM_BYTES  (SMEM_FLOATS * 4)  // 56832

template<bool ACC, bool RELU>
__global__ void __launch_bounds__(256)
sgemm_kernel(const float* __restrict__ A, const float* __restrict__ B,
             const float* __restrict__ Cin, float* __restrict__ D,
             int M, int N, int K, float alpha)
{
    extern __shared__ float sm[];
    const uint32_t smbase = (uint32_t)__cvta_generic_to_shared(sm);

    const int tid  = threadIdx.x;
    const int bm   = blockIdx.y * BM;
    const int bn   = blockIdx.x * BN;

    const int warp = tid >> 5;
    const int lane = tid & 31;
    const int wm   = (warp >> 2) * 64;   // 0 / 64
    const int wn   = (warp & 3) * 32;    // 0/32/64/96
    const int g    = lane >> 2;          // 0..7
    const int tg   = lane & 3;           // 0..3

    // cp.async chunk mapping (16B chunks, 2 A-chunks + 2 B-chunks per thread)
    const int chA0 = tid * 2;
    const int aR0  = chA0 >> 2, aC0 = (chA0 & 3) * 4;
    const int aR1  = (chA0 + 1) >> 2, aC1 = ((chA0 + 1) & 3) * 4;
    const int bR0  = chA0 >> 5, bC0 = (chA0 & 31) * 4;
    const int bR1  = (chA0 + 1) >> 5, bC1 = ((chA0 + 1) & 31) * 4;

    float c[4][4][4];
#pragma unroll
    for (int i = 0; i < 4; i++)
#pragma unroll
        for (int j = 0; j < 4; j++)
#pragma unroll
            for (int r = 0; r < 4; r++) c[i][j][r] = 0.f;

    const int nkt = K >> 4;

    auto load_stage = [&](int s, int kt) {
        const uint32_t aBase = smbase + (s * A_STAGE) * 4;
        const uint32_t bBase = smbase + (B_BASE + s * B_STAGE) * 4;
        cp_async16(aBase + (aR0 * AROW + aC0) * 4,
                   A + (size_t)(bm + aR0) * K + kt * BK + aC0, bm + aR0 < M);
        cp_async16(aBase + (aR1 * AROW + aC1) * 4,
                   A + (size_t)(bm + aR1) * K + kt * BK + aC1, bm + aR1 < M);
        cp_async16(bBase + (bR0 * BROW + bC0) * 4,
                   B + (size_t)(kt * BK + bR0) * N + bn + bC0, true);
        cp_async16(bBase + (bR1 * BROW + bC1) * 4,
                   B + (size_t)(kt * BK + bR1) * N + bn + bC1, true);
        CP_COMMIT();
    };

    load_stage(0, 0);
    load_stage(1, 1);

    for (int kt = 0; kt < nkt; kt++) {
        const int s = kt % 3;
        CP_WAIT1();
        __syncthreads();
        if (kt + 2 < nkt) load_stage((kt + 2) % 3, kt + 2);

        const float* Asb = sm + s * A_STAGE;
        const float* Bsb = sm + B_BASE + s * B_STAGE;

#pragma unroll
        for (int ks = 0; ks < 2; ks++) {
            const int k0 = ks * 8;
            uint32_t a[4][4], b[4][2];
#pragma unroll
            for (int i = 0; i < 4; i++) {
                const float* p = Asb + (wm + i * 16 + g) * AROW + k0 + tg;
                a[i][0] = __float_as_uint(p[0]);
                a[i][2] = __float_as_uint(p[4]);
                a[i][1] = __float_as_uint(p[8 * AROW]);
                a[i][3] = __float_as_uint(p[8 * AROW + 4]);
            }
#pragma unroll
            for (int j = 0; j < 4; j++) {
                const float* p = Bsb + (k0 + tg) * BROW + wn + j * 8 + g;
                b[j][0] = __float_as_uint(p[0]);
                b[j][1] = __float_as_uint(p[4 * BROW]);
            }
#pragma unroll
            for (int i = 0; i < 4; i++)
#pragma unroll
                for (int j = 0; j < 4; j++)
                    mma_tf32(c[i][j][0], c[i][j][1], c[i][j][2], c[i][j][3],
                             a[i][0], a[i][1], a[i][2], a[i][3],
                             b[j][0], b[j][1]);
        }
        __syncthreads();
    }

    // ---- epilogue: C fragment m16n8: rows g / g+8, cols 2tg, 2tg+1 ----
#pragma unroll
    for (int i = 0; i < 4; i++) {
        int r0 = bm + wm + i * 16 + g;
        int r1 = r0 + 8;
#pragma unroll
        for (int j = 0; j < 4; j++) {
            int col = bn + wn + j * 8 + 2 * tg;
            if (r0 < M) {
                float2 v;
                v.x = c[i][j][0] * alpha;
                v.y = c[i][j][1] * alpha;
                if (ACC) {
                    float2 cc = *(const float2*)(Cin + (size_t)r0 * N + col);
                    v.x += cc.x; v.y += cc.y;
                }
                if (RELU) { v.x = fmaxf(v.x, 0.f); v.y = fmaxf(v.y, 0.f); }
                *(float2*)(D + (size_t)r0 * N + col) = v;
            }
            if (r1 < M) {
                float2 v;
                v.x = c[i][j][2] * alpha;
                v.y = c[i][j][3] * alpha;
                if (ACC) {
                    float2 cc = *(const float2*)(Cin + (size_t)r1 * N + col);
                    v.x += cc.x; v.y += cc.y;
                }
                if (RELU) { v.x = fmaxf(v.x, 0.f); v.y = fmaxf(v.y, 0.f); }
                *(float2*)(D + (size_t)r1 * N + col) = v;
            }
        }
    }
}

// ---------------- small helper kernels -------------------------------------
__global__ void embed_kernel(const int* __restrict__ tx,
                             const float* __restrict__ table,
                             float* __restrict__ h)
{
    int idx = blockIdx.x * blockDim.x + threadIdx.x;
    if (idx >= NN * (EMBD / 4)) return;
    int n = idx >> 6;
    int c = idx & 63;
    int i0 = tx[n * 3 + 0], i1 = tx[n * 3 + 1], i2 = tx[n * 3 + 2];
    const float4* t4 = (const float4*)table;
    float4 a = t4[(size_t)i0 * 64 + c];
    float4 b = t4[(size_t)i1 * 64 + c];
    float4 d = t4[(size_t)i2 * 64 + c];
    float4 o;
    o.x = a.x + b.x + d.x; o.y = a.y + b.y + d.y;
    o.z = a.z + b.z + d.z; o.w = a.w + b.w + d.w;
    ((float4*)h)[idx] = o;
}

__global__ void transpose_k(const float* __restrict__ k, float* __restrict__ kT)
{
    int i = blockIdx.x * blockDim.x + threadIdx.x;
    if (i >= MM * EMBD) return;
    int r = i >> 8;
    int c = i & 255;
    kT[(size_t)c * MM + r] = k[i];
}

__global__ void zero_kernel(float4* __restrict__ p, int n4)
{
    int i = blockIdx.x * blockDim.x + threadIdx.x;
    if (i < n4) p[i] = make_float4(0.f, 0.f, 0.f, 0.f);
}

__global__ void scatter_edges(const int* __restrict__ ei, const int* __restrict__ et,
                              const float* __restrict__ h, float* __restrict__ tmp)
{
    int idx = blockIdx.x * blockDim.x + threadIdx.x;
    if (idx >= EE * (EMBD / 4)) return;
    int e = idx >> 6;
    int c = idx & 63;
    int src = ei[e];
    int tgt = ei[EE + e];
    int t   = et[e];
    float4 v = ((const float4*)(h + (size_t)src * EMBD))[c];
    float* dst = tmp + ((size_t)tgt * NSLT + t) * EMBD + (size_t)c * 4;
    atomicAdd(dst + 0, v.x);
    atomicAdd(dst + 1, v.y);
    atomicAdd(dst + 2, v.z);
    atomicAdd(dst + 3, v.w);
}

__device__ __forceinline__ float warp_max(float v) {
#pragma unroll
    for (int o = 16; o; o >>= 1) v = fmaxf(v, __shfl_xor_sync(0xffffffffu, v, o));
    return v;
}
__device__ __forceinline__ float warp_sum(float v) {
#pragma unroll
    for (int o = 16; o; o >>= 1) v += __shfl_xor_sync(0xffffffffu, v, o);
    return v;
}

// in-place softmax over rows of width 1024; 256 threads/block, 1 block/row
__global__ void softmax1024(float* __restrict__ S)
{
    __shared__ float shm[8];
    __shared__ float shs[8];
    size_t row = blockIdx.x;
    float4* p = (float4*)(S + row * MM);
    int tid = threadIdx.x;
    int wid = tid >> 5, lane = tid & 31;

    float4 x = p[tid];
    float m = fmaxf(fmaxf(x.x, x.y), fmaxf(x.z, x.w));
    m = warp_max(m);
    if (lane == 0) shm[wid] = m;
    __syncthreads();
    if (tid == 0) {
        float v = shm[0];
#pragma unroll
        for (int i = 1; i < 8; i++) v = fmaxf(v, shm[i]);
        shm[0] = v;
    }
    __syncthreads();
    m = shm[0];

    float4 e;
    e.x = __expf(x.x - m); e.y = __expf(x.y - m);
    e.z = __expf(x.z - m); e.w = __expf(x.w - m);
    float s = e.x + e.y + e.z + e.w;
    s = warp_sum(s);
    if (lane == 0) shs[wid] = s;
    __syncthreads();
    if (tid == 0) {
        float v = 0.f;
#pragma unroll
        for (int i = 0; i < 8; i++) v += shs[i];
        shs[0] = v;
    }
    __syncthreads();
    float inv = 1.f / shs[0];
    e.x *= inv; e.y *= inv; e.z *= inv; e.w *= inv;
    p[tid] = e;
}

// log_softmax over rows of width 512 with bias; 128 threads/block, 1 block/row
__global__ void log_softmax512(const float* __restrict__ logits,
                               const float* __restrict__ bias,
                               float* __restrict__ out)
{
    __shared__ float shm[4];
    __shared__ float shs[4];
    size_t row = blockIdx.x;
    const float4* p = (const float4*)(logits + row * VOC);
    const float4* b4 = (const float4*)bias;
    float4* o = (float4*)(out + row * VOC);
    int tid = threadIdx.x;
    int wid = tid >> 5, lane = tid & 31;

    float4 x = p[tid];
    float4 b = b4[tid];
    x.x += b.x; x.y += b.y; x.z += b.z; x.w += b.w;

    float m = fmaxf(fmaxf(x.x, x.y), fmaxf(x.z, x.w));
    m = warp_max(m);
    if (lane == 0) shm[wid] = m;
    __syncthreads();
    if (tid == 0) shm[0] = fmaxf(fmaxf(shm[0], shm[1]), fmaxf(shm[2], shm[3]));
    __syncthreads();
    m = shm[0];

    float s = __expf(x.x - m) + __expf(x.y - m) + __expf(x.z - m) + __expf(x.w - m);
    s = warp_sum(s);
    if (lane == 0) shs[wid] = s;
    __syncthreads();
    if (tid == 0) shs[0] = shs[0] + shs[1] + shs[2] + shs[3];
    __syncthreads();
    float lse = m + __logf(shs[0]);

    x.x -= lse; x.y -= lse; x.z -= lse; x.w -= lse;
    o[tid] = x;
}

// edge head: one warp per edge
__global__ void edge_head(const float* __restrict__ h, const int* __restrict__ ei,
                          const float* __restrict__ Wg, const float* __restrict__ bg,
                          float* __restrict__ out)
{
    __shared__ float sW[2 * EMBD * NSRT];
    __shared__ float sb[NSRT];
    for (int i = threadIdx.x; i < 2 * EMBD * NSRT; i += blockDim.x) sW[i] = Wg[i];
    if (threadIdx.x < NSRT) sb[threadIdx.x] = bg[threadIdx.x];
    __syncthreads();

    int e = blockIdx.x * 8 + (threadIdx.x >> 5);
    int lane = threadIdx.x & 31;
    if (e >= EE) return;
    int src = ei[e];
    int tgt = ei[EE + e];
    const float* hs = h + (size_t)src * EMBD;
    const float* ht = h + (size_t)tgt * EMBD;

    float s[NSRT] = {0.f, 0.f, 0.f, 0.f, 0.f};
    for (int d = lane; d < EMBD; d += 32) {
        float a = hs[d];
        float b = ht[d];
#pragma unroll
        for (int r = 0; r < NSRT; r++)
            s[r] += a * sW[d * NSRT + r] + b * sW[(EMBD + d) * NSRT + r];
    }
#pragma unroll
    for (int r = 0; r < NSRT; r++) s[r] = warp_sum(s[r]);

    if (lane == 0) {
#pragma unroll
        for (int r = 0; r < NSRT; r++) s[r] += sb[r];
        float m = s[0];
#pragma unroll
        for (int r = 1; r < NSRT; r++) m = fmaxf(m, s[r]);
        float sum = 0.f;
#pragma unroll
        for (int r = 0; r < NSRT; r++) sum += __expf(s[r] - m);
        float lse = m + __logf(sum);
#pragma unroll
        for (int r = 0; r < NSRT; r++)
            out[(size_t)e * NSRT + r] = s[r] - lse;
    }
}

// ---------------- host orchestration ---------------------------------------
static void run_sgemm(const float* A, const float* B, const float* Cin, float* D,
                      int M, int N, int K, float alpha, bool acc, bool relu)
{
    dim3 grid(N / BN, (M + BM - 1) / BM);
    if (acc) {
        if (relu) {
            cudaFuncSetAttribute(sgemm_kernel<true, true>,
                                 cudaFuncAttributeMaxDynamicSharedMemorySize, SMEM_BYTES);
            sgemm_kernel<true, true ><<<grid, 256, SMEM_BYTES>>>(A, B, Cin, D, M, N, K, alpha);
        } else {
            cudaFuncSetAttribute(sgemm_kernel<true, false>,
                                 cudaFuncAttributeMaxDynamicSharedMemorySize, SMEM_BYTES);
            sgemm_kernel<true, false><<<grid, 256, SMEM_BYTES>>>(A, B, Cin, D, M, N, K, alpha);
        }
    } else {
        cudaFuncSetAttribute(sgemm_kernel<false, false>,
                             cudaFuncAttributeMaxDynamicSharedMemorySize, SMEM_BYTES);
        sgemm_kernel<false, false><<<grid, 256, SMEM_BYTES>>>(A, B, nullptr, D, M, N, K, alpha);
    }
}

static void run_layer(const float* hin, float* hout,
                      const float* x, const int* ei, const int* et,
                      const float* W_h, const float* W_rel, const float* W_src,
                      float* kbuf, float* kTbuf, float* Sbuf, float* ctxbuf,
                      bool compute_k)
{
    if (compute_k) {
        run_sgemm(x, W_src, nullptr, kbuf, MM, EMBD, HIDD, 1.f, false, false);
        transpose_k<<<(MM * EMBD + 255) / 256, 256>>>(kbuf, kTbuf);
    }
    // S = (h @ kT) / 16   [N,1024]  K=256
    run_sgemm(hin, kTbuf, nullptr, Sbuf, NN, MM, EMBD, 0.0625f, false, false);
    softmax1024<<<NN, 256>>>(Sbuf);
    // ctx = S @ k   [N,256]  K=1024
    run_sgemm(Sbuf, kbuf, nullptr, ctxbuf, NN, EMBD, MM, 1.f, false, false);
    // tmp scatter: tmp[tgt,type,:] += h[src,:]
    zero_kernel<<<(NN * MM / 4 + 255) / 256, 256>>>((float4*)Sbuf, NN * MM / 4);
    scatter_edges<<<(EE * (EMBD / 4) + 255) / 256, 256>>>(ei, et, hin, Sbuf);
    // ctx += tmp_flat @ W_rel_flat   [N,256]  K=1024
    run_sgemm(Sbuf, W_rel, ctxbuf, ctxbuf, NN, EMBD, NSLT * EMBD, 1.f, true, false);
    // hout = relu(hin @ W_h + ctx)   [N,256]  K=256
    run_sgemm(hin, W_h, ctxbuf, hout, NN, EMBD, EMBD, 1.f, true, true);
}

extern "C" void kernel_launch(void* const* d_in, const int* in_sizes, int n_in,
                              void* d_out, int out_size)
{
    const int*   tgt_x  = (const int*)  d_in[0];
    const float* x      = (const float*)d_in[1];
    const int*   ei     = (const int*)  d_in[2];
    const int*   et     = (const int*)  d_in[3];
    const float* table  = (const float*)d_in[4];
    const float* W_h1   = (const float*)d_in[5];
    const float* W_rel1 = (const float*)d_in[6];
    const float* W_src1 = (const float*)d_in[7];
    const float* W_h3   = (const float*)d_in[8];
    const float* W_rel3 = (const float*)d_in[9];
    const float* W_src3 = (const float*)d_in[10];
    const float* Wz     = (const float*)d_in[11];
    const float* bz     = (const float*)d_in[12];
    const float* Wg     = (const float*)d_in[13];
    const float* bg     = (const float*)d_in[14];
    float* out = (float*)d_out;

    float *hA, *hB, *ctx, *S, *k, *kT;
    cudaGetSymbolAddress((void**)&hA,  g_hA);
    cudaGetSymbolAddress((void**)&hB,  g_hB);
    cudaGetSymbolAddress((void**)&ctx, g_ctx);
    cudaGetSymbolAddress((void**)&S,   g_S);
    cudaGetSymbolAddress((void**)&k,   g_k);
    cudaGetSymbolAddress((void**)&kT,  g_kT);

    // h0 = sum_l embed_table[tgt_x[:,l]]
    embed_kernel<<<(NN * (EMBD / 4) + 255) / 256, 256>>>(tgt_x, table, hA);

    run_layer(hA, hB, x, ei, et, W_h1, W_rel1, W_src1, k, kT, S, ctx, true);
    run_layer(hB, hA, x, ei, et, W_h1, W_rel1, W_src1, k, kT, S, ctx, false);
    run_layer(hA, hB, x, ei, et, W_h3, W_rel3, W_src3, k, kT, S, ctx, true);

    // node head: logits = h @ Wz
    run_sgemm(hB, Wz, nullptr, S, NN, VOC, EMBD, 1.f, false, false);
    log_softmax512<<<NN, 128>>>(S, bz, out);

    // edge head
    edge_head<<<(EE + 7) / 8, 256>>>(hB, ei, Wg, bg, out + (size_t)NN * VOC);
}